// round 2
// baseline (speedup 1.0000x reference)
#include <cuda_runtime.h>
#include <math.h>
#include <stdint.h>

// Problem constants
#define BB 2
#define SS 2048
#define HH 1024
#define FF 2816
#define EE 8
#define KK 2
#define TT (BB*SS)          // 4096 tokens
#define SLOTS (TT*KK)       // 8192 token-slots
#define BM 64               // row tile (slots)
#define PADMAX (SLOTS + EE*BM)   // 8704 worst-case padded rows
#define ROW_TILES_MAX (PADMAX/BM) // 136

// ---------------- device scratch (static, allowed) ----------------
__device__ float g_h1[(size_t)PADMAX * FF];   // hidden after silu(gate)*up  (~98MB)
__device__ float g_y [(size_t)PADMAX * HH];   // expert outputs per slot-row (~36MB)
__device__ int   g_count[EE];
__device__ int   g_fill[EE];
__device__ float g_psum[EE];
__device__ int   g_base[EE+1];                // padded bases, g_base[EE] = total padded rows
__device__ int   g_sorted_token[PADMAX];      // token id per sorted row (0 for pad rows)
__device__ int   g_slot_row[SLOTS];           // (t,k) -> sorted row
__device__ int   g_tok_e[SLOTS];
__device__ float g_tok_w[SLOTS];

// ---------------- init: reset counters each launch ----------------
__global__ void init_kernel() {
    int i = blockIdx.x * blockDim.x + threadIdx.x;
    if (i < PADMAX) g_sorted_token[i] = 0;
    if (i < EE) { g_count[i] = 0; g_fill[i] = 0; g_psum[i] = 0.f; }
}

// ---------------- router: logits, top-2, softmax weights, aux stats ----------------
__global__ void router_kernel(const float* __restrict__ x, const float* __restrict__ rw) {
    int t = blockIdx.x;
    __shared__ float sp[128][EE];
    float acc[EE];
#pragma unroll
    for (int e = 0; e < EE; e++) acc[e] = 0.f;
    const float* xt = x + (size_t)t * HH;
    for (int h = threadIdx.x; h < HH; h += 128) {
        float xv = xt[h];
#pragma unroll
        for (int e = 0; e < EE; e++) acc[e] += xv * rw[e*HH + h];
    }
#pragma unroll
    for (int e = 0; e < EE; e++) sp[threadIdx.x][e] = acc[e];
    __syncthreads();
    for (int s = 64; s > 0; s >>= 1) {
        if (threadIdx.x < s) {
#pragma unroll
            for (int e = 0; e < EE; e++) sp[threadIdx.x][e] += sp[threadIdx.x + s][e];
        }
        __syncthreads();
    }
    if (threadIdx.x == 0) {
        float lg[EE];
#pragma unroll
        for (int e = 0; e < EE; e++) lg[e] = sp[0][e];
        // top-2, first occurrence wins ties (matches lax.top_k)
        int i0 = 0;
#pragma unroll
        for (int e = 1; e < EE; e++) if (lg[e] > lg[i0]) i0 = e;
        int i1 = -1;
#pragma unroll
        for (int e = 0; e < EE; e++) {
            if (e == i0) continue;
            if (i1 < 0 || lg[e] > lg[i1]) i1 = e;
        }
        float ex = expf(lg[i1] - lg[i0]);
        float w0 = 1.f / (1.f + ex);
        float w1 = ex / (1.f + ex);
        g_tok_e[2*t]   = i0;  g_tok_e[2*t+1] = i1;
        g_tok_w[2*t]   = w0;  g_tok_w[2*t+1] = w1;
        atomicAdd(&g_count[i0], 1);
        atomicAdd(&g_count[i1], 1);
        // full softmax for aux loss
        float m = lg[0];
#pragma unroll
        for (int e = 1; e < EE; e++) m = fmaxf(m, lg[e]);
        float s = 0.f;
        float pe[EE];
#pragma unroll
        for (int e = 0; e < EE; e++) { pe[e] = expf(lg[e] - m); s += pe[e]; }
        float inv = 1.f / s;
#pragma unroll
        for (int e = 0; e < EE; e++) atomicAdd(&g_psum[e], pe[e] * inv);
    }
}

// ---------------- setup: padded prefix bases + aux loss ----------------
__global__ void setup_kernel(float* __restrict__ out_aux) {
    if (threadIdx.x == 0) {
        int base = 0;
        for (int e = 0; e < EE; e++) {
            g_base[e] = base;
            int pc = (g_count[e] + BM - 1) & ~(BM - 1);
            base += pc;
        }
        g_base[EE] = base;
        float aux = 0.f;
        for (int e = 0; e < EE; e++) {
            float f = (float)g_count[e] / (float)SLOTS;
            float P = g_psum[e] / (float)TT;
            aux += f * P;
        }
        out_aux[0] = aux * (float)EE;
    }
}

// ---------------- scatter slots into expert-sorted rows ----------------
__global__ void scatter_kernel() {
    int s = blockIdx.x * blockDim.x + threadIdx.x;
    if (s >= SLOTS) return;
    int e = g_tok_e[s];
    int pos = atomicAdd(&g_fill[e], 1);
    int row = g_base[e] + pos;
    g_sorted_token[row] = s >> 1;
    g_slot_row[s] = row;
}

// ---------------- GEMM1: h1 = silu(x@Wg) * (x@Wu), grouped by expert ----------------
__global__ __launch_bounds__(256) void gemm1_kernel(
    const float* __restrict__ x,
    const float* __restrict__ wg,
    const float* __restrict__ wu)
{
    int rt = blockIdx.x;           // row tile (fastest -> L2 reuse of B tiles)
    int nt = blockIdx.y;           // F tile
    int total = g_base[EE];
    int r0 = rt * BM;
    if (r0 >= total) return;
    int e = 0;
    while (g_base[e+1] <= r0) e++;
    const float* Wg = wg + (size_t)e * HH * FF;
    const float* Wu = wu + (size_t)e * HH * FF;
    int n0 = nt * 64;

    __shared__ float As[16][64];
    __shared__ float Bg[16][64];
    __shared__ float Bu[16][64];
    __shared__ int   s_tok[64];

    int tid = threadIdx.x;
    if (tid < 64) s_tok[tid] = g_sorted_token[r0 + tid];
    __syncthreads();

    int tx = tid & 15, ty = tid >> 4;
    int arow = tid >> 2, akq = tid & 3;      // A loader: row 0..63, quad 0..3
    int brow = tid >> 4, bcol = (tid & 15) * 4; // B loader: row 0..15, col quad

    float accg[4][4], accu[4][4];
#pragma unroll
    for (int i = 0; i < 4; i++)
#pragma unroll
        for (int j = 0; j < 4; j++) { accg[i][j] = 0.f; accu[i][j] = 0.f; }

    const float* xrow = x + (size_t)s_tok[arow] * HH;

    for (int kk = 0; kk < HH; kk += 16) {
        float4 av = *(const float4*)(xrow + kk + akq * 4);
        As[akq*4+0][arow] = av.x;
        As[akq*4+1][arow] = av.y;
        As[akq*4+2][arow] = av.z;
        As[akq*4+3][arow] = av.w;
        *(float4*)&Bg[brow][bcol] = *(const float4*)(Wg + (size_t)(kk + brow) * FF + n0 + bcol);
        *(float4*)&Bu[brow][bcol] = *(const float4*)(Wu + (size_t)(kk + brow) * FF + n0 + bcol);
        __syncthreads();
#pragma unroll
        for (int k = 0; k < 16; k++) {
            float4 a  = *(float4*)&As[k][ty*4];
            float4 bg = *(float4*)&Bg[k][tx*4];
            float4 bu = *(float4*)&Bu[k][tx*4];
            float ar[4] = {a.x, a.y, a.z, a.w};
            float bgr[4] = {bg.x, bg.y, bg.z, bg.w};
            float bur[4] = {bu.x, bu.y, bu.z, bu.w};
#pragma unroll
            for (int i = 0; i < 4; i++)
#pragma unroll
                for (int j = 0; j < 4; j++) {
                    accg[i][j] += ar[i] * bgr[j];
                    accu[i][j] += ar[i] * bur[j];
                }
        }
        __syncthreads();
    }
#pragma unroll
    for (int i = 0; i < 4; i++) {
        size_t rowoff = (size_t)(r0 + ty*4 + i) * FF + n0;
#pragma unroll
        for (int j = 0; j < 4; j++) {
            float g = accg[i][j];
            float u = accu[i][j];
            float h = (g / (1.f + expf(-g))) * u;
            g_h1[rowoff + tx*4 + j] = h;
        }
    }
}

// ---------------- GEMM2: y = h1 @ Wd, grouped by expert ----------------
__global__ __launch_bounds__(256) void gemm2_kernel(const float* __restrict__ wd)
{
    int rt = blockIdx.x;
    int nt = blockIdx.y;
    int total = g_base[EE];
    int r0 = rt * BM;
    if (r0 >= total) return;
    int e = 0;
    while (g_base[e+1] <= r0) e++;
    const float* Wd = wd + (size_t)e * FF * HH;
    int n0 = nt * 64;

    __shared__ float As[16][64];
    __shared__ float Bs[16][64];

    int tid = threadIdx.x;
    int tx = tid & 15, ty = tid >> 4;
    int arow = tid >> 2, akq = tid & 3;
    int brow = tid >> 4, bcol = (tid & 15) * 4;

    float acc[4][4];
#pragma unroll
    for (int i = 0; i < 4; i++)
#pragma unroll
        for (int j = 0; j < 4; j++) acc[i][j] = 0.f;

    const float* arowp = g_h1 + (size_t)(r0 + arow) * FF;

    for (int kk = 0; kk < FF; kk += 16) {
        float4 av = *(const float4*)(arowp + kk + akq * 4);
        As[akq*4+0][arow] = av.x;
        As[akq*4+1][arow] = av.y;
        As[akq*4+2][arow] = av.z;
        As[akq*4+3][arow] = av.w;
        *(float4*)&Bs[brow][bcol] = *(const float4*)(Wd + (size_t)(kk + brow) * HH + n0 + bcol);
        __syncthreads();
#pragma unroll
        for (int k = 0; k < 16; k++) {
            float4 a = *(float4*)&As[k][ty*4];
            float4 b = *(float4*)&Bs[k][tx*4];
            float ar[4] = {a.x, a.y, a.z, a.w};
            float br[4] = {b.x, b.y, b.z, b.w};
#pragma unroll
            for (int i = 0; i < 4; i++)
#pragma unroll
                for (int j = 0; j < 4; j++)
                    acc[i][j] += ar[i] * br[j];
        }
        __syncthreads();
    }
#pragma unroll
    for (int i = 0; i < 4; i++) {
        size_t rowoff = (size_t)(r0 + ty*4 + i) * HH + n0;
#pragma unroll
        for (int j = 0; j < 4; j++)
            g_y[rowoff + tx*4 + j] = acc[i][j];
    }
}

// ---------------- combine: out[t] = w0*y[slot0] + w1*y[slot1] ----------------
__global__ void combine_kernel(float* __restrict__ out) {
    int i = blockIdx.x * blockDim.x + threadIdx.x;   // over T * H/4
    if (i >= TT * (HH/4)) return;
    int t = i / (HH/4);
    int c = (i - t * (HH/4)) * 4;
    int r0 = g_slot_row[2*t], r1 = g_slot_row[2*t+1];
    float w0 = g_tok_w[2*t], w1 = g_tok_w[2*t+1];
    float4 y0 = *(const float4*)(g_y + (size_t)r0 * HH + c);
    float4 y1 = *(const float4*)(g_y + (size_t)r1 * HH + c);
    float4 o;
    o.x = w0*y0.x + w1*y1.x;
    o.y = w0*y0.y + w1*y1.y;
    o.z = w0*y0.z + w1*y1.z;
    o.w = w0*y0.w + w1*y1.w;
    *(float4*)(out + (size_t)t * HH + c) = o;
}

// ---------------- launch ----------------
extern "C" void kernel_launch(void* const* d_in, const int* in_sizes, int n_in,
                              void* d_out, int out_size) {
    const float* x  = (const float*)d_in[0];
    const float* rw = (const float*)d_in[1];
    const float* wg = (const float*)d_in[2];
    const float* wu = (const float*)d_in[3];
    const float* wd = (const float*)d_in[4];
    float* out = (float*)d_out;

    init_kernel<<<(PADMAX + 255) / 256, 256>>>();
    router_kernel<<<TT, 128>>>(x, rw);
    setup_kernel<<<1, 32>>>(out + (size_t)TT * HH);
    scatter_kernel<<<(SLOTS + 255) / 256, 256>>>();
    gemm1_kernel<<<dim3(ROW_TILES_MAX, FF/64), 256>>>(x, wg, wu);
    gemm2_kernel<<<dim3(ROW_TILES_MAX, HH/64), 256>>>(wd);
    combine_kernel<<<(TT * (HH/4) + 255) / 256, 256>>>(out);
}

// round 7
// speedup vs baseline: 1.0186x; 1.0186x over previous
#include <cuda_runtime.h>
#include <math.h>
#include <stdint.h>

// Problem constants
#define BB 2
#define SS 2048
#define HH 1024
#define FF 2816
#define EE 8
#define KK 2
#define TT (BB*SS)          // 4096 tokens
#define SLOTS (TT*KK)       // 8192 token-slots
#define BM 64               // row tile (slots)
#define PADMAX (SLOTS + EE*BM)   // 8704 worst-case padded rows
#define ROW_TILES_MAX (PADMAX/BM) // 136

typedef unsigned long long u64;

// ---------------- device scratch ----------------
__device__ float g_h1[(size_t)PADMAX * FF];
__device__ float g_y [(size_t)PADMAX * HH];
__device__ int   g_count[EE];
__device__ int   g_fill[EE];
__device__ float g_psum[EE];
__device__ int   g_base[EE+1];
__device__ int   g_sorted_token[PADMAX];
__device__ int   g_slot_row[SLOTS];
__device__ int   g_tok_e[SLOTS];
__device__ float g_tok_w[SLOTS];

// ---------------- f32x2 packed helpers ----------------
__device__ __forceinline__ u64 pack2(float x) {
    u64 r; asm("mov.b64 %0, {%1, %1};" : "=l"(r) : "f"(x)); return r;
}
__device__ __forceinline__ void fma2(u64& d, u64 a, u64 b) {
    asm("fma.rn.f32x2 %0, %1, %2, %0;" : "+l"(d) : "l"(a), "l"(b));
}

// ---------------- init ----------------
__global__ void init_kernel() {
    int i = blockIdx.x * blockDim.x + threadIdx.x;
    if (i < PADMAX) g_sorted_token[i] = 0;
    if (i < EE) { g_count[i] = 0; g_fill[i] = 0; g_psum[i] = 0.f; }
}

// ---------------- router ----------------
__global__ void router_kernel(const float* __restrict__ x, const float* __restrict__ rw) {
    int t = blockIdx.x;
    __shared__ float sp[128][EE];
    float acc[EE];
#pragma unroll
    for (int e = 0; e < EE; e++) acc[e] = 0.f;
    const float* xt = x + (size_t)t * HH;
    for (int h = threadIdx.x; h < HH; h += 128) {
        float xv = xt[h];
#pragma unroll
        for (int e = 0; e < EE; e++) acc[e] += xv * rw[e*HH + h];
    }
#pragma unroll
    for (int e = 0; e < EE; e++) sp[threadIdx.x][e] = acc[e];
    __syncthreads();
    for (int s = 64; s > 0; s >>= 1) {
        if (threadIdx.x < s) {
#pragma unroll
            for (int e = 0; e < EE; e++) sp[threadIdx.x][e] += sp[threadIdx.x + s][e];
        }
        __syncthreads();
    }
    if (threadIdx.x == 0) {
        float lg[EE];
#pragma unroll
        for (int e = 0; e < EE; e++) lg[e] = sp[0][e];
        int i0 = 0;
#pragma unroll
        for (int e = 1; e < EE; e++) if (lg[e] > lg[i0]) i0 = e;
        int i1 = -1;
#pragma unroll
        for (int e = 0; e < EE; e++) {
            if (e == i0) continue;
            if (i1 < 0 || lg[e] > lg[i1]) i1 = e;
        }
        float ex = expf(lg[i1] - lg[i0]);
        float w0 = 1.f / (1.f + ex);
        float w1 = ex / (1.f + ex);
        g_tok_e[2*t]   = i0;  g_tok_e[2*t+1] = i1;
        g_tok_w[2*t]   = w0;  g_tok_w[2*t+1] = w1;
        atomicAdd(&g_count[i0], 1);
        atomicAdd(&g_count[i1], 1);
        float m = lg[0];
#pragma unroll
        for (int e = 1; e < EE; e++) m = fmaxf(m, lg[e]);
        float s = 0.f;
        float pe[EE];
#pragma unroll
        for (int e = 0; e < EE; e++) { pe[e] = expf(lg[e] - m); s += pe[e]; }
        float inv = 1.f / s;
#pragma unroll
        for (int e = 0; e < EE; e++) atomicAdd(&g_psum[e], pe[e] * inv);
    }
}

// ---------------- setup ----------------
__global__ void setup_kernel(float* __restrict__ out_aux) {
    if (threadIdx.x == 0) {
        int base = 0;
        for (int e = 0; e < EE; e++) {
            g_base[e] = base;
            int pc = (g_count[e] + BM - 1) & ~(BM - 1);
            base += pc;
        }
        g_base[EE] = base;
        float aux = 0.f;
        for (int e = 0; e < EE; e++) {
            float f = (float)g_count[e] / (float)SLOTS;
            float P = g_psum[e] / (float)TT;
            aux += f * P;
        }
        out_aux[0] = aux * (float)EE;
    }
}

// ---------------- scatter ----------------
__global__ void scatter_kernel() {
    int s = blockIdx.x * blockDim.x + threadIdx.x;
    if (s >= SLOTS) return;
    int e = g_tok_e[s];
    int pos = atomicAdd(&g_fill[e], 1);
    int row = g_base[e] + pos;
    g_sorted_token[row] = s >> 1;
    g_slot_row[s] = row;
}

// ---------------- GEMM1: h1 = silu(x@Wg) * (x@Wu), f32x2 packed FMA ----------------
__global__ __launch_bounds__(256) void gemm1_kernel(
    const float* __restrict__ x,
    const float* __restrict__ wg,
    const float* __restrict__ wu)
{
    int rt = blockIdx.x;
    int nt = blockIdx.y;
    int total = g_base[EE];
    int r0 = rt * BM;
    if (r0 >= total) return;
    int e = 0;
    while (g_base[e+1] <= r0) e++;
    const float* Wg = wg + (size_t)e * HH * FF;
    const float* Wu = wu + (size_t)e * HH * FF;
    int n0 = nt * 64;

    __shared__ float As[16][64];
    __shared__ float Bg[16][64];
    __shared__ float Bu[16][64];
    __shared__ int   s_tok[64];

    int tid = threadIdx.x;
    if (tid < 64) s_tok[tid] = g_sorted_token[r0 + tid];
    __syncthreads();

    int tx = tid & 15, ty = tid >> 4;
    int arow = tid >> 2, akq = tid & 3;
    int brow = tid >> 4, bcol = (tid & 15) * 4;

    // packed accumulators: [i][jp] covers cols (jp*2, jp*2+1)
    u64 accg[4][2], accu[4][2];
#pragma unroll
    for (int i = 0; i < 4; i++) {
        accg[i][0] = 0ull; accg[i][1] = 0ull;
        accu[i][0] = 0ull; accu[i][1] = 0ull;
    }

    const float* xrow = x + (size_t)s_tok[arow] * HH;

    for (int kk = 0; kk < HH; kk += 16) {
        float4 av = *(const float4*)(xrow + kk + akq * 4);
        As[akq*4+0][arow] = av.x;
        As[akq*4+1][arow] = av.y;
        As[akq*4+2][arow] = av.z;
        As[akq*4+3][arow] = av.w;
        *(float4*)&Bg[brow][bcol] = *(const float4*)(Wg + (size_t)(kk + brow) * FF + n0 + bcol);
        *(float4*)&Bu[brow][bcol] = *(const float4*)(Wu + (size_t)(kk + brow) * FF + n0 + bcol);
        __syncthreads();
#pragma unroll
        for (int k = 0; k < 16; k++) {
            float4 a = *(float4*)&As[k][ty*4];
            ulonglong2 bg = *(const ulonglong2*)&Bg[k][tx*4];
            ulonglong2 bu = *(const ulonglong2*)&Bu[k][tx*4];
            float ar[4] = {a.x, a.y, a.z, a.w};
#pragma unroll
            for (int i = 0; i < 4; i++) {
                u64 aa = pack2(ar[i]);
                fma2(accg[i][0], aa, bg.x);
                fma2(accg[i][1], aa, bg.y);
                fma2(accu[i][0], aa, bu.x);
                fma2(accu[i][1], aa, bu.y);
            }
        }
        __syncthreads();
    }
#pragma unroll
    for (int i = 0; i < 4; i++) {
        size_t rowoff = (size_t)(r0 + ty*4 + i) * FF + n0;
#pragma unroll
        for (int jp = 0; jp < 2; jp++) {
            float2 gv = *(float2*)&accg[i][jp];
            float2 uv = *(float2*)&accu[i][jp];
            float h0 = (gv.x / (1.f + expf(-gv.x))) * uv.x;
            float h1 = (gv.y / (1.f + expf(-gv.y))) * uv.y;
            *(float2*)&g_h1[rowoff + tx*4 + jp*2] = make_float2(h0, h1);
        }
    }
}

// ---------------- GEMM2: y = h1 @ Wd, f32x2 packed FMA ----------------
__global__ __launch_bounds__(256) void gemm2_kernel(const float* __restrict__ wd)
{
    int rt = blockIdx.x;
    int nt = blockIdx.y;
    int total = g_base[EE];
    int r0 = rt * BM;
    if (r0 >= total) return;
    int e = 0;
    while (g_base[e+1] <= r0) e++;
    const float* Wd = wd + (size_t)e * FF * HH;
    int n0 = nt * 64;

    __shared__ float As[16][64];
    __shared__ float Bs[16][64];

    int tid = threadIdx.x;
    int tx = tid & 15, ty = tid >> 4;
    int arow = tid >> 2, akq = tid & 3;
    int brow = tid >> 4, bcol = (tid & 15) * 4;

    u64 acc[4][2];
#pragma unroll
    for (int i = 0; i < 4; i++) { acc[i][0] = 0ull; acc[i][1] = 0ull; }

    const float* arowp = g_h1 + (size_t)(r0 + arow) * FF;

    for (int kk = 0; kk < FF; kk += 16) {
        float4 av = *(const float4*)(arowp + kk + akq * 4);
        As[akq*4+0][arow] = av.x;
        As[akq*4+1][arow] = av.y;
        As[akq*4+2][arow] = av.z;
        As[akq*4+3][arow] = av.w;
        *(float4*)&Bs[brow][bcol] = *(const float4*)(Wd + (size_t)(kk + brow) * HH + n0 + bcol);
        __syncthreads();
#pragma unroll
        for (int k = 0; k < 16; k++) {
            float4 a = *(float4*)&As[k][ty*4];
            ulonglong2 b = *(const ulonglong2*)&Bs[k][tx*4];
            float ar[4] = {a.x, a.y, a.z, a.w};
#pragma unroll
            for (int i = 0; i < 4; i++) {
                u64 aa = pack2(ar[i]);
                fma2(acc[i][0], aa, b.x);
                fma2(acc[i][1], aa, b.y);
            }
        }
        __syncthreads();
    }
#pragma unroll
    for (int i = 0; i < 4; i++) {
        size_t rowoff = (size_t)(r0 + ty*4 + i) * HH + n0;
#pragma unroll
        for (int jp = 0; jp < 2; jp++) {
            float2 v = *(float2*)&acc[i][jp];
            *(float2*)&g_y[rowoff + tx*4 + jp*2] = v;
        }
    }
}

// ---------------- combine ----------------
__global__ void combine_kernel(float* __restrict__ out) {
    int i = blockIdx.x * blockDim.x + threadIdx.x;
    if (i >= TT * (HH/4)) return;
    int t = i / (HH/4);
    int c = (i - t * (HH/4)) * 4;
    int r0 = g_slot_row[2*t], r1 = g_slot_row[2*t+1];
    float w0 = g_tok_w[2*t], w1 = g_tok_w[2*t+1];
    float4 y0 = *(const float4*)(g_y + (size_t)r0 * HH + c);
    float4 y1 = *(const float4*)(g_y + (size_t)r1 * HH + c);
    float4 o;
    o.x = w0*y0.x + w1*y1.x;
    o.y = w0*y0.y + w1*y1.y;
    o.z = w0*y0.z + w1*y1.z;
    o.w = w0*y0.w + w1*y1.w;
    *(float4*)(out + (size_t)t * HH + c) = o;
}

// ---------------- launch ----------------
extern "C" void kernel_launch(void* const* d_in, const int* in_sizes, int n_in,
                              void* d_out, int out_size) {
    const float* x  = (const float*)d_in[0];
    const float* rw = (const float*)d_in[1];
    const float* wg = (const float*)d_in[2];
    const float* wu = (const float*)d_in[3];
    const float* wd = (const float*)d_in[4];
    float* out = (float*)d_out;

    init_kernel<<<(PADMAX + 255) / 256, 256>>>();
    router_kernel<<<TT, 128>>>(x, rw);
    setup_kernel<<<1, 32>>>(out + (size_t)TT * HH);
    scatter_kernel<<<(SLOTS + 255) / 256, 256>>>();
    gemm1_kernel<<<dim3(ROW_TILES_MAX, FF/64), 256>>>(x, wg, wu);
    gemm2_kernel<<<dim3(ROW_TILES_MAX, HH/64), 256>>>(wd);
    combine_kernel<<<(TT * (HH/4) + 255) / 256, 256>>>(out);
}

// round 8
// speedup vs baseline: 1.2107x; 1.1886x over previous
#include <cuda_runtime.h>
#include <math.h>
#include <stdint.h>

#define BB 2
#define SS 2048
#define HH 1024
#define FF 2816
#define EE 8
#define KK 2
#define TT (BB*SS)
#define SLOTS (TT*KK)
#define BM 128
#define PADMAX (SLOTS + EE*BM)    // 9216
#define RT_MAX (PADMAX/BM)        // 72

typedef unsigned long long u64;

__device__ float g_h1[(size_t)PADMAX * FF];
__device__ float g_y [(size_t)PADMAX * HH];
__device__ int   g_count[EE];
__device__ int   g_fill[EE];
__device__ float g_psum[EE];
__device__ int   g_base[EE+1];
__device__ int   g_sorted_token[PADMAX];
__device__ int   g_slot_row[SLOTS];
__device__ int   g_tok_e[SLOTS];
__device__ float g_tok_w[SLOTS];

__device__ __forceinline__ u64 pack2(float x) {
    u64 r; asm("mov.b64 %0, {%1, %1};" : "=l"(r) : "f"(x)); return r;
}
__device__ __forceinline__ void fma2(u64& d, u64 a, u64 b) {
    asm("fma.rn.f32x2 %0, %1, %2, %0;" : "+l"(d) : "l"(a), "l"(b));
}
__device__ __forceinline__ uint32_t smem_u32(const void* p) {
    uint32_t a;
    asm("{ .reg .u64 t; cvta.to.shared.u64 t, %1; cvt.u32.u64 %0, t; }" : "=r"(a) : "l"(p));
    return a;
}
__device__ __forceinline__ void cp16(uint32_t dst, const void* src) {
    asm volatile("cp.async.cg.shared.global [%0], [%1], 16;"
                 :: "r"(dst), "l"(__cvta_generic_to_global(src)) : "memory");
}
#define CP_COMMIT() asm volatile("cp.async.commit_group;" ::: "memory")
#define CP_WAIT1()  asm volatile("cp.async.wait_group 1;" ::: "memory")
#define CP_WAIT0()  asm volatile("cp.async.wait_group 0;" ::: "memory")

__global__ void init_kernel() {
    int i = blockIdx.x * blockDim.x + threadIdx.x;
    if (i < PADMAX) g_sorted_token[i] = 0;
    if (i < EE) { g_count[i] = 0; g_fill[i] = 0; g_psum[i] = 0.f; }
}

__global__ void router_kernel(const float* __restrict__ x, const float* __restrict__ rw) {
    int t = blockIdx.x;
    __shared__ float sp[128][EE];
    float acc[EE];
#pragma unroll
    for (int e = 0; e < EE; e++) acc[e] = 0.f;
    const float* xt = x + (size_t)t * HH;
    for (int h = threadIdx.x; h < HH; h += 128) {
        float xv = xt[h];
#pragma unroll
        for (int e = 0; e < EE; e++) acc[e] += xv * rw[e*HH + h];
    }
#pragma unroll
    for (int e = 0; e < EE; e++) sp[threadIdx.x][e] = acc[e];
    __syncthreads();
    for (int s = 64; s > 0; s >>= 1) {
        if (threadIdx.x < s)
#pragma unroll
            for (int e = 0; e < EE; e++) sp[threadIdx.x][e] += sp[threadIdx.x + s][e];
        __syncthreads();
    }
    if (threadIdx.x == 0) {
        float lg[EE];
#pragma unroll
        for (int e = 0; e < EE; e++) lg[e] = sp[0][e];
        int i0 = 0;
#pragma unroll
        for (int e = 1; e < EE; e++) if (lg[e] > lg[i0]) i0 = e;
        int i1 = -1;
#pragma unroll
        for (int e = 0; e < EE; e++) {
            if (e == i0) continue;
            if (i1 < 0 || lg[e] > lg[i1]) i1 = e;
        }
        float ex = expf(lg[i1] - lg[i0]);
        g_tok_e[2*t] = i0;  g_tok_e[2*t+1] = i1;
        g_tok_w[2*t] = 1.f/(1.f+ex);  g_tok_w[2*t+1] = ex/(1.f+ex);
        atomicAdd(&g_count[i0], 1);
        atomicAdd(&g_count[i1], 1);
        float m = lg[0];
#pragma unroll
        for (int e = 1; e < EE; e++) m = fmaxf(m, lg[e]);
        float s = 0.f, pe[EE];
#pragma unroll
        for (int e = 0; e < EE; e++) { pe[e] = expf(lg[e] - m); s += pe[e]; }
        float inv = 1.f / s;
#pragma unroll
        for (int e = 0; e < EE; e++) atomicAdd(&g_psum[e], pe[e] * inv);
    }
}

__global__ void setup_kernel(float* __restrict__ out_aux) {
    if (threadIdx.x == 0) {
        int base = 0;
        for (int e = 0; e < EE; e++) {
            g_base[e] = base;
            base += (g_count[e] + BM - 1) & ~(BM - 1);
        }
        g_base[EE] = base;
        float aux = 0.f;
        for (int e = 0; e < EE; e++)
            aux += ((float)g_count[e] / SLOTS) * (g_psum[e] / TT);
        out_aux[0] = aux * EE;
    }
}

__global__ void scatter_kernel() {
    int s = blockIdx.x * blockDim.x + threadIdx.x;
    if (s >= SLOTS) return;
    int e = g_tok_e[s];
    int row = g_base[e] + atomicAdd(&g_fill[e], 1);
    g_sorted_token[row] = s >> 1;
    g_slot_row[s] = row;
}

// ---- GEMM1: h1 = silu(x@Wg)*(x@Wu). CTA 128M x 64N(each mat), thread 8M x 4N x2 ----
__global__ __launch_bounds__(256) void gemm1_kernel(
    const float* __restrict__ x, const float* __restrict__ wg, const float* __restrict__ wu)
{
    int r0 = blockIdx.x * BM;
    if (r0 >= g_base[EE]) return;
    int n0 = blockIdx.y * 64;
    int e = 0;
    while (g_base[e+1] <= r0) e++;
    const float* Wg = wg + (size_t)e * HH * FF;
    const float* Wu = wu + (size_t)e * HH * FF;

    __shared__ float As[2][16][132];
    __shared__ float Bg[2][16][64];
    __shared__ float Bu[2][16][64];
    __shared__ int s_tok[128];

    int tid = threadIdx.x;
    if (tid < 128) s_tok[tid] = g_sorted_token[r0 + tid];
    __syncthreads();

    int am = tid & 127, akh = (tid >> 7) * 8;
    const float* arow = x + (size_t)s_tok[am] * HH + akh;
    int brow = tid >> 4, bq = tid & 15;
    int tn = tid & 15, tm = tid >> 4;

    // prologue: chunks 0,1
#pragma unroll
    for (int pc = 0; pc < 2; pc++) {
        float4 p0 = *(const float4*)(arow + pc*16);
        float4 p1 = *(const float4*)(arow + pc*16 + 4);
        float av[8] = {p0.x,p0.y,p0.z,p0.w,p1.x,p1.y,p1.z,p1.w};
#pragma unroll
        for (int j = 0; j < 8; j++) As[pc][akh+j][am] = av[j];
        size_t bo = (size_t)(pc*16 + brow) * FF + n0 + bq*4;
        cp16(smem_u32(&Bg[pc][brow][bq*4]), Wg + bo);
        cp16(smem_u32(&Bu[pc][brow][bq*4]), Wu + bo);
        CP_COMMIT();
    }

    u64 hg[8][2], hu[8][2];
#pragma unroll
    for (int j = 0; j < 8; j++) { hg[j][0]=0; hg[j][1]=0; hu[j][0]=0; hu[j][1]=0; }

    const int chunks = HH/16;  // 64
    float4 nx0, nx1;
    for (int c = 0; c < chunks; c++) {
        int s = c & 1;
        if (c == chunks-1) CP_WAIT0(); else CP_WAIT1();
        __syncthreads();
        if (c + 2 < chunks) {
            nx0 = *(const float4*)(arow + (c+2)*16);
            nx1 = *(const float4*)(arow + (c+2)*16 + 4);
        }
#pragma unroll
        for (int k = 0; k < 16; k++) {
            float4 a01 = *(float4*)&As[s][k][tm*8];
            float4 a23 = *(float4*)&As[s][k][tm*8+4];
            ulonglong2 bgv = *(ulonglong2*)&Bg[s][k][tn*4];
            ulonglong2 buv = *(ulonglong2*)&Bu[s][k][tn*4];
            float av[8] = {a01.x,a01.y,a01.z,a01.w,a23.x,a23.y,a23.z,a23.w};
#pragma unroll
            for (int j = 0; j < 8; j++) {
                u64 pa = pack2(av[j]);
                fma2(hg[j][0], pa, bgv.x);
                fma2(hg[j][1], pa, bgv.y);
                fma2(hu[j][0], pa, buv.x);
                fma2(hu[j][1], pa, buv.y);
            }
        }
        __syncthreads();
        if (c + 2 < chunks) {
            float av[8] = {nx0.x,nx0.y,nx0.z,nx0.w,nx1.x,nx1.y,nx1.z,nx1.w};
#pragma unroll
            for (int j = 0; j < 8; j++) As[s][akh+j][am] = av[j];
            size_t bo = (size_t)((c+2)*16 + brow) * FF + n0 + bq*4;
            cp16(smem_u32(&Bg[s][brow][bq*4]), Wg + bo);
            cp16(smem_u32(&Bu[s][brow][bq*4]), Wu + bo);
            CP_COMMIT();
        }
    }

#pragma unroll
    for (int j = 0; j < 8; j++) {
        int row = r0 + tm*8 + j;
        float2 g0 = *(float2*)&hg[j][0], g1 = *(float2*)&hg[j][1];
        float2 u0 = *(float2*)&hu[j][0], u1 = *(float2*)&hu[j][1];
        float4 o;
        o.x = (g0.x / (1.f + expf(-g0.x))) * u0.x;
        o.y = (g0.y / (1.f + expf(-g0.y))) * u0.y;
        o.z = (g1.x / (1.f + expf(-g1.x))) * u1.x;
        o.w = (g1.y / (1.f + expf(-g1.y))) * u1.y;
        *(float4*)&g_h1[(size_t)row * FF + n0 + tn*4] = o;
    }
}

// ---- GEMM2: y = h1 @ Wd. CTA 128M x 128N, thread 8M x 8N ----
__global__ __launch_bounds__(256) void gemm2_kernel(const float* __restrict__ wd)
{
    int r0 = blockIdx.x * BM;
    if (r0 >= g_base[EE]) return;
    int n0 = blockIdx.y * 128;
    int e = 0;
    while (g_base[e+1] <= r0) e++;
    const float* Wd = wd + (size_t)e * FF * HH;

    __shared__ float As[2][16][132];
    __shared__ float Bs[2][16][128];

    int tid = threadIdx.x;
    int am = tid & 127, akh = (tid >> 7) * 8;
    const float* arow = g_h1 + (size_t)(r0 + am) * FF + akh;
    int brow = tid >> 4, bq = tid & 15;
    int tn = tid & 15, tm = tid >> 4;

#pragma unroll
    for (int pc = 0; pc < 2; pc++) {
        float4 p0 = *(const float4*)(arow + pc*16);
        float4 p1 = *(const float4*)(arow + pc*16 + 4);
        float av[8] = {p0.x,p0.y,p0.z,p0.w,p1.x,p1.y,p1.z,p1.w};
#pragma unroll
        for (int j = 0; j < 8; j++) As[pc][akh+j][am] = av[j];
        size_t bo = (size_t)(pc*16 + brow) * HH + n0 + bq*8;
        cp16(smem_u32(&Bs[pc][brow][bq*8]), Wd + bo);
        cp16(smem_u32(&Bs[pc][brow][bq*8+4]), Wd + bo + 4);
        CP_COMMIT();
    }

    u64 d[8][4];
#pragma unroll
    for (int j = 0; j < 8; j++) { d[j][0]=0; d[j][1]=0; d[j][2]=0; d[j][3]=0; }

    const int chunks = FF/16;  // 176
    float4 nx0, nx1;
    for (int c = 0; c < chunks; c++) {
        int s = c & 1;
        if (c == chunks-1) CP_WAIT0(); else CP_WAIT1();
        __syncthreads();
        if (c + 2 < chunks) {
            nx0 = *(const float4*)(arow + (c+2)*16);
            nx1 = *(const float4*)(arow + (c+2)*16 + 4);
        }
#pragma unroll
        for (int k = 0; k < 16; k++) {
            float4 a01 = *(float4*)&As[s][k][tm*8];
            float4 a23 = *(float4*)&As[s][k][tm*8+4];
            ulonglong2 b01 = *(ulonglong2*)&Bs[s][k][tn*8];
            ulonglong2 b23 = *(ulonglong2*)&Bs[s][k][tn*8+4];
            float av[8] = {a01.x,a01.y,a01.z,a01.w,a23.x,a23.y,a23.z,a23.w};
#pragma unroll
            for (int j = 0; j < 8; j++) {
                u64 pa = pack2(av[j]);
                fma2(d[j][0], pa, b01.x);
                fma2(d[j][1], pa, b01.y);
                fma2(d[j][2], pa, b23.x);
                fma2(d[j][3], pa, b23.y);
            }
        }
        __syncthreads();
        if (c + 2 < chunks) {
            float av[8] = {nx0.x,nx0.y,nx0.z,nx0.w,nx1.x,nx1.y,nx1.z,nx1.w};
#pragma unroll
            for (int j = 0; j < 8; j++) As[s][akh+j][am] = av[j];
            size_t bo = (size_t)((c+2)*16 + brow) * HH + n0 + bq*8;
            cp16(smem_u32(&Bs[s][brow][bq*8]), Wd + bo);
            cp16(smem_u32(&Bs[s][brow][bq*8+4]), Wd + bo + 4);
            CP_COMMIT();
        }
    }

#pragma unroll
    for (int j = 0; j < 8; j++) {
        size_t ro = (size_t)(r0 + tm*8 + j) * HH + n0 + tn*8;
        float2 v0 = *(float2*)&d[j][0], v1 = *(float2*)&d[j][1];
        float2 v2 = *(float2*)&d[j][2], v3 = *(float2*)&d[j][3];
        *(float4*)&g_y[ro]     = make_float4(v0.x, v0.y, v1.x, v1.y);
        *(float4*)&g_y[ro + 4] = make_float4(v2.x, v2.y, v3.x, v3.y);
    }
}

__global__ void combine_kernel(float* __restrict__ out) {
    int i = blockIdx.x * blockDim.x + threadIdx.x;
    if (i >= TT * (HH/4)) return;
    int t = i / (HH/4);
    int c = (i - t * (HH/4)) * 4;
    int r0 = g_slot_row[2*t], r1 = g_slot_row[2*t+1];
    float w0 = g_tok_w[2*t], w1 = g_tok_w[2*t+1];
    float4 y0 = *(const float4*)(g_y + (size_t)r0 * HH + c);
    float4 y1 = *(const float4*)(g_y + (size_t)r1 * HH + c);
    float4 o;
    o.x = w0*y0.x + w1*y1.x;  o.y = w0*y0.y + w1*y1.y;
    o.z = w0*y0.z + w1*y1.z;  o.w = w0*y0.w + w1*y1.w;
    *(float4*)(out + (size_t)t * HH + c) = o;
}

extern "C" void kernel_launch(void* const* d_in, const int* in_sizes, int n_in,
                              void* d_out, int out_size) {
    const float* x  = (const float*)d_in[0];
    const float* rw = (const float*)d_in[1];
    const float* wg = (const float*)d_in[2];
    const float* wu = (const float*)d_in[3];
    const float* wd = (const float*)d_in[4];
    float* out = (float*)d_out;

    init_kernel<<<(PADMAX + 255) / 256, 256>>>();
    router_kernel<<<TT, 128>>>(x, rw);
    setup_kernel<<<1, 32>>>(out + (size_t)TT * HH);
    scatter_kernel<<<(SLOTS + 255) / 256, 256>>>();
    gemm1_kernel<<<dim3(RT_MAX, FF/64), 256>>>(x, wg, wu);
    gemm2_kernel<<<dim3(RT_MAX, HH/128), 256>>>(wd);
    combine_kernel<<<(TT * (HH/4) + 255) / 256, 256>>>(out);
}